// round 14
// baseline (speedup 1.0000x reference)
#include <cuda_runtime.h>
#include <math.h>

#define S 2048
#define B 64
#define H 1024
#define NSPLIT 8     // CTAs per batch element in phase 1
#define WPB 8        // warps per block
#define NSK1 16      // k-splits fc1
#define NSK2 8       // k-splits fc2

// ---------------- scratch (device globals; no allocation) ----------------
__device__ __align__(16) float g_part_acc[B * NSPLIT * H];
__device__ float g_part_m[B * NSPLIT];
__device__ float g_part_l[B * NSPLIT];
__device__ __align__(16) float g_xin[B * 2 * H];      // [attn | key]
__device__ __align__(16) float g_part1[NSK1 * B * H];
__device__ __align__(16) float g_y[B * H];
__device__ __align__(16) float g_t[B * H];
__device__ __align__(16) float g_part2[NSK2 * B * H];

// ---------------- phase 1: fused scores + online softmax + weighted sum ----
__global__ __launch_bounds__(256) void k_attn(const float* __restrict__ ctx,
                                              const float* __restrict__ key,
                                              const float* __restrict__ mask,
                                              float* __restrict__ at_raw)
{
    const int b    = blockIdx.y;
    const int warp = threadIdx.x >> 5;
    const int lane = threadIdx.x & 31;
    const int wg   = blockIdx.x * WPB + warp;   // 0..63 warps per b

    // lane owns h = 4*lane + 128*k, k=0..7
    const float4* key4 = (const float4*)(key + b * H);
    float4 kreg[8];
#pragma unroll
    for (int k = 0; k < 8; k++) kreg[k] = key4[lane + 32 * k];

    float4 acc[8];
#pragma unroll
    for (int k = 0; k < 8; k++) acc[k] = make_float4(0.f, 0.f, 0.f, 0.f);
    float m = -3.0e38f, l = 0.f;

    const int NW = NSPLIT * WPB;  // 64
#pragma unroll 1
    for (int s = wg; s < S; s += NW) {
        const float4* row = (const float4*)(ctx + ((long)s * B + b) * H);
        float4 c[8];
#pragma unroll
        for (int k = 0; k < 8; k++) c[k] = row[lane + 32 * k];
        float p = 0.f;
#pragma unroll
        for (int k = 0; k < 8; k++)
            p += c[k].x * kreg[k].x + c[k].y * kreg[k].y +
                 c[k].z * kreg[k].z + c[k].w * kreg[k].w;
#pragma unroll
        for (int off = 16; off >= 1; off >>= 1)
            p += __shfl_xor_sync(0xffffffffu, p, off);
        p += mask[b * S + s];
        if (lane == 0) at_raw[b * S + s] = p;   // raw score, normalized later
        if (p > m) {
            float sc = __expf(m - p);           // first iter: exp(-huge)=0
#pragma unroll
            for (int k = 0; k < 8; k++) {
                acc[k].x *= sc; acc[k].y *= sc; acc[k].z *= sc; acc[k].w *= sc;
            }
            l *= sc;
            m = p;
        }
        float w = __expf(p - m);
        l += w;
#pragma unroll
        for (int k = 0; k < 8; k++) {
            acc[k].x += w * c[k].x; acc[k].y += w * c[k].y;
            acc[k].z += w * c[k].z; acc[k].w += w * c[k].w;
        }
    }

    // CTA-level combine of 8 warp partials
    __shared__ float4 s_acc[WPB][H / 4];  // 32KB
    __shared__ float s_m[WPB], s_l[WPB];
#pragma unroll
    for (int k = 0; k < 8; k++) s_acc[warp][lane + 32 * k] = acc[k];
    if (lane == 0) { s_m[warp] = m; s_l[warp] = l; }
    __syncthreads();

    const int t = threadIdx.x;
    float M = -3.0e38f;
#pragma unroll
    for (int w = 0; w < WPB; w++) M = fmaxf(M, s_m[w]);
    float L = 0.f;
    float4 a = make_float4(0.f, 0.f, 0.f, 0.f);
#pragma unroll
    for (int w = 0; w < WPB; w++) {
        float sc = __expf(s_m[w] - M);
        L += sc * s_l[w];
        float4 v = s_acc[w][t];
        a.x += sc * v.x; a.y += sc * v.y; a.z += sc * v.z; a.w += sc * v.w;
    }
    ((float4*)g_part_acc)[(b * NSPLIT + blockIdx.x) * (H / 4) + t] = a;
    if (t == 0) {
        g_part_m[b * NSPLIT + blockIdx.x] = M;
        g_part_l[b * NSPLIT + blockIdx.x] = L;
    }
}

// ---------------- phase 2: combine splits, build xin, normalize At ---------
__global__ __launch_bounds__(256) void k_finish(const float* __restrict__ key,
                                                float* __restrict__ at)
{
    const int b = blockIdx.x;
    const int t = threadIdx.x;
    float pm[NSPLIT];
    float M = -3.0e38f;
#pragma unroll
    for (int i = 0; i < NSPLIT; i++) {
        pm[i] = g_part_m[b * NSPLIT + i];
        M = fmaxf(M, pm[i]);
    }
    float L = 0.f;
#pragma unroll
    for (int i = 0; i < NSPLIT; i++) L += __expf(pm[i] - M) * g_part_l[b * NSPLIT + i];
    float4 a = make_float4(0.f, 0.f, 0.f, 0.f);
#pragma unroll
    for (int i = 0; i < NSPLIT; i++) {
        float sc = __expf(pm[i] - M);
        float4 v = ((const float4*)g_part_acc)[(b * NSPLIT + i) * (H / 4) + t];
        a.x += sc * v.x; a.y += sc * v.y; a.z += sc * v.z; a.w += sc * v.w;
    }
    float invL = 1.f / L;
    a.x *= invL; a.y *= invL; a.z *= invL; a.w *= invL;
    ((float4*)g_xin)[b * (2 * H / 4) + t] = a;                              // attn
    ((float4*)g_xin)[b * (2 * H / 4) + 256 + t] = ((const float4*)key)[b * (H / 4) + t]; // key
#pragma unroll
    for (int r = 0; r < S / 256; r++) {
        int s = t + r * 256;
        at[b * S + s] = __expf(at[b * S + s] - M) * invL;
    }
}

// ---------------- small split-K SGEMM: C_part[ks] = A(64xK) * W(1024xK)^T ---
template<int K, int NSK>
__device__ __forceinline__ void gemm_body(const float* __restrict__ A,
                                          const float* __restrict__ W,
                                          float* __restrict__ Cp)
{
    __shared__ float As[32][68];   // [k][b], padded
    __shared__ float Ws[32][68];   // [k][j], padded
    const int jb = blockIdx.x * 64;
    const int kbase0 = blockIdx.y * (K / NSK);
    const int t = threadIdx.x;
    const int tx = t & 15, ty = t >> 4;
    float c[4][4];
#pragma unroll
    for (int i = 0; i < 4; i++)
#pragma unroll
        for (int j = 0; j < 4; j++) c[i][j] = 0.f;

#pragma unroll 1
    for (int kb = 0; kb < K / NSK; kb += 32) {
        const int kbase = kbase0 + kb;
#pragma unroll
        for (int i = 0; i < 8; i++) {
            int g = t + i * 256;
            As[g & 31][g >> 5] = A[(g >> 5) * K + kbase + (g & 31)];
        }
#pragma unroll
        for (int i = 0; i < 8; i++) {
            int g = t + i * 256;
            Ws[g & 31][g >> 5] = W[(jb + (g >> 5)) * K + kbase + (g & 31)];
        }
        __syncthreads();
#pragma unroll
        for (int kk = 0; kk < 32; kk++) {
            float4 av = *(const float4*)&As[kk][ty * 4];
            float4 wv = *(const float4*)&Ws[kk][tx * 4];
            c[0][0] += av.x * wv.x; c[0][1] += av.x * wv.y; c[0][2] += av.x * wv.z; c[0][3] += av.x * wv.w;
            c[1][0] += av.y * wv.x; c[1][1] += av.y * wv.y; c[1][2] += av.y * wv.z; c[1][3] += av.y * wv.w;
            c[2][0] += av.z * wv.x; c[2][1] += av.z * wv.y; c[2][2] += av.z * wv.z; c[2][3] += av.z * wv.w;
            c[3][0] += av.w * wv.x; c[3][1] += av.w * wv.y; c[3][2] += av.w * wv.z; c[3][3] += av.w * wv.w;
        }
        __syncthreads();
    }
#pragma unroll
    for (int mi = 0; mi < 4; mi++) {
        float4 v = make_float4(c[mi][0], c[mi][1], c[mi][2], c[mi][3]);
        *(float4*)(Cp + ((long)blockIdx.y * B + ty * 4 + mi) * H + jb + tx * 4) = v;
    }
}

__global__ __launch_bounds__(256) void k_fc1(const float* __restrict__ W)
{
    gemm_body<2 * H, NSK1>(g_xin, W, g_part1);
}

__global__ __launch_bounds__(256) void k_fc2(const float* __restrict__ W)
{
    gemm_body<H, NSK2>(g_t, W, g_part2);
}

// ---------------- reduce fc1 partials + bias -------------------------------
__global__ __launch_bounds__(256) void k_red1(const float* __restrict__ fc1_b)
{
    const int b = blockIdx.x, t = threadIdx.x;
    float4 y = ((const float4*)fc1_b)[t];
#pragma unroll
    for (int s2 = 0; s2 < NSK1; s2++) {
        float4 p = ((const float4*)g_part1)[(s2 * B + b) * (H / 4) + t];
        y.x += p.x; y.y += p.y; y.z += p.z; y.w += p.w;
    }
    ((float4*)g_y)[b * (H / 4) + t] = y;
}

// ---------------- batch-norm (training stats, biased var) + tanh -----------
__global__ __launch_bounds__(256) void k_bn(const float* __restrict__ gamma,
                                            const float* __restrict__ beta)
{
    const int t  = threadIdx.x;
    const int jj = t >> 6;            // 0..3
    const int b  = t & 63;
    const int j  = blockIdx.x * 4 + jj;
    float y  = g_y[b * H + j];
    float s1 = y, s2 = y * y;
#pragma unroll
    for (int off = 16; off >= 1; off >>= 1) {
        s1 += __shfl_xor_sync(0xffffffffu, s1, off);
        s2 += __shfl_xor_sync(0xffffffffu, s2, off);
    }
    __shared__ float sm1[8], sm2[8];
    const int warp = t >> 5;
    if ((t & 31) == 0) { sm1[warp] = s1; sm2[warp] = s2; }
    __syncthreads();
    float S1 = sm1[jj * 2] + sm1[jj * 2 + 1];
    float S2 = sm2[jj * 2] + sm2[jj * 2 + 1];
    float mean = S1 * (1.f / 64.f);
    float var  = S2 * (1.f / 64.f) - mean * mean;
    float rstd = rsqrtf(var + 1e-5f);
    g_t[b * H + j] = tanhf((y - mean) * rstd * gamma[j] + beta[j]);
}

// ---------------- reduce fc2 partials + bias -> x output -------------------
__global__ __launch_bounds__(256) void k_out(const float* __restrict__ fc2_b,
                                             float* __restrict__ x)
{
    const int b = blockIdx.x, t = threadIdx.x;
    float4 v = ((const float4*)fc2_b)[t];
#pragma unroll
    for (int s2 = 0; s2 < NSK2; s2++) {
        float4 p = ((const float4*)g_part2)[(s2 * B + b) * (H / 4) + t];
        v.x += p.x; v.y += p.y; v.z += p.z; v.w += p.w;
    }
    ((float4*)x)[b * (H / 4) + t] = v;
}

// ---------------------------------------------------------------------------
extern "C" void kernel_launch(void* const* d_in, const int* in_sizes, int n_in,
                              void* d_out, int out_size)
{
    (void)in_sizes; (void)n_in; (void)out_size;
    const float* ctx   = (const float*)d_in[0];
    const float* key   = (const float*)d_in[1];
    const float* mask  = (const float*)d_in[2];
    const float* fc1_w = (const float*)d_in[3];
    const float* fc1_b = (const float*)d_in[4];
    const float* gamma = (const float*)d_in[5];
    const float* beta  = (const float*)d_in[6];
    const float* fc2_w = (const float*)d_in[7];
    const float* fc2_b = (const float*)d_in[8];

    float* out    = (float*)d_out;
    float* x_out  = out;            // (B, H)
    float* at_out = out + B * H;    // (B, S)

    k_attn  <<<dim3(NSPLIT, B), 256>>>(ctx, key, mask, at_out);
    k_finish<<<B, 256>>>(key, at_out);
    k_fc1   <<<dim3(H / 64, NSK1), 256>>>(fc1_w);
    k_red1  <<<B, 256>>>(fc1_b);
    k_bn    <<<H / 4, 256>>>(gamma, beta);
    k_fc2   <<<dim3(H / 64, NSK2), 256>>>(fc2_w);
    k_out   <<<B, 256>>>(fc2_b, x_out);
}

// round 15
// speedup vs baseline: 1.0469x; 1.0469x over previous
#include <cuda_runtime.h>
#include <math.h>

#define S 2048
#define B 64
#define H 1024
#define NSPLIT 4     // CTAs per batch element in phase 1 (256 CTAs = 1 wave @ occ 2)
#define WPB 8        // warps per block
#define NSK1 16      // k-splits fc1
#define NSK2 16      // k-splits fc2

// ---------------- scratch (device globals; no allocation) ----------------
__device__ __align__(16) float g_part_acc[B * NSPLIT * H];
__device__ float g_part_m[B * NSPLIT];
__device__ float g_part_l[B * NSPLIT];
__device__ __align__(16) float g_xin[B * 2 * H];      // [attn | key]
__device__ __align__(16) float g_part1[NSK1 * B * H];
__device__ __align__(16) float g_y[B * H];
__device__ __align__(16) float g_t[B * H];
__device__ __align__(16) float g_part2[NSK2 * B * H];

// ---------------- phase 1: fused scores + online softmax + weighted sum ----
__global__ __launch_bounds__(256, 2) void k_attn(const float* __restrict__ ctx,
                                                 const float* __restrict__ key,
                                                 const float* __restrict__ mask,
                                                 float* __restrict__ at_raw)
{
    const int b    = blockIdx.y;
    const int warp = threadIdx.x >> 5;
    const int lane = threadIdx.x & 31;
    const int wg   = blockIdx.x * WPB + warp;   // 0..31 warp-slots per b

    __shared__ float4 s_key[H / 4];             // 4KB: key[b], shared by all warps
    __shared__ float4 s_acc[WPB][H / 4];        // 32KB combine buffer
    __shared__ float  s_m[WPB], s_l[WPB];

    s_key[threadIdx.x] = ((const float4*)(key + b * H))[threadIdx.x];
    __syncthreads();

    float4 acc[8];
#pragma unroll
    for (int k = 0; k < 8; k++) acc[k] = make_float4(0.f, 0.f, 0.f, 0.f);
    float m = -3.0e38f, l = 0.f;

    const int NW = NSPLIT * WPB;  // 32
#pragma unroll 1
    for (int s = wg; s < S; s += NW) {
        const float4* row = (const float4*)(ctx + ((long)s * B + b) * H);
        float4 c[8];
#pragma unroll
        for (int k = 0; k < 8; k++) c[k] = row[lane + 32 * k];
        float p = 0.f;
#pragma unroll
        for (int k = 0; k < 8; k++) {
            float4 kv = s_key[lane + 32 * k];
            p += c[k].x * kv.x + c[k].y * kv.y + c[k].z * kv.z + c[k].w * kv.w;
        }
#pragma unroll
        for (int off = 16; off >= 1; off >>= 1)
            p += __shfl_xor_sync(0xffffffffu, p, off);
        p += mask[b * S + s];
        if (lane == 0) at_raw[b * S + s] = p;   // raw score, normalized later
        if (p > m) {
            float sc = __expf(m - p);           // first iter: exp(-huge)=0
#pragma unroll
            for (int k = 0; k < 8; k++) {
                acc[k].x *= sc; acc[k].y *= sc; acc[k].z *= sc; acc[k].w *= sc;
            }
            l *= sc;
            m = p;
        }
        float w = __expf(p - m);
        l += w;
#pragma unroll
        for (int k = 0; k < 8; k++) {
            acc[k].x += w * c[k].x; acc[k].y += w * c[k].y;
            acc[k].z += w * c[k].z; acc[k].w += w * c[k].w;
        }
    }

    // CTA-level combine of 8 warp partials
#pragma unroll
    for (int k = 0; k < 8; k++) s_acc[warp][lane + 32 * k] = acc[k];
    if (lane == 0) { s_m[warp] = m; s_l[warp] = l; }
    __syncthreads();

    const int t = threadIdx.x;
    float M = -3.0e38f;
#pragma unroll
    for (int w = 0; w < WPB; w++) M = fmaxf(M, s_m[w]);
    float L = 0.f;
    float4 a = make_float4(0.f, 0.f, 0.f, 0.f);
#pragma unroll
    for (int w = 0; w < WPB; w++) {
        float sc = __expf(s_m[w] - M);
        L += sc * s_l[w];
        float4 v = s_acc[w][t];
        a.x += sc * v.x; a.y += sc * v.y; a.z += sc * v.z; a.w += sc * v.w;
    }
    ((float4*)g_part_acc)[(b * NSPLIT + blockIdx.x) * (H / 4) + t] = a;
    if (t == 0) {
        g_part_m[b * NSPLIT + blockIdx.x] = M;
        g_part_l[b * NSPLIT + blockIdx.x] = L;
    }
}

// ---------------- phase 2: combine splits, build xin, normalize At ---------
__global__ __launch_bounds__(256) void k_finish(const float* __restrict__ key,
                                                float* __restrict__ at)
{
    const int b = blockIdx.x;
    const int t = threadIdx.x;
    float pm[NSPLIT];
    float M = -3.0e38f;
#pragma unroll
    for (int i = 0; i < NSPLIT; i++) {
        pm[i] = g_part_m[b * NSPLIT + i];
        M = fmaxf(M, pm[i]);
    }
    float L = 0.f;
#pragma unroll
    for (int i = 0; i < NSPLIT; i++) L += __expf(pm[i] - M) * g_part_l[b * NSPLIT + i];
    float4 a = make_float4(0.f, 0.f, 0.f, 0.f);
#pragma unroll
    for (int i = 0; i < NSPLIT; i++) {
        float sc = __expf(pm[i] - M);
        float4 v = ((const float4*)g_part_acc)[(b * NSPLIT + i) * (H / 4) + t];
        a.x += sc * v.x; a.y += sc * v.y; a.z += sc * v.z; a.w += sc * v.w;
    }
    float invL = 1.f / L;
    a.x *= invL; a.y *= invL; a.z *= invL; a.w *= invL;
    ((float4*)g_xin)[b * (2 * H / 4) + t] = a;                              // attn
    ((float4*)g_xin)[b * (2 * H / 4) + 256 + t] = ((const float4*)key)[b * (H / 4) + t]; // key
#pragma unroll
    for (int r = 0; r < S / 256; r++) {
        int s = t + r * 256;
        at[b * S + s] = __expf(at[b * S + s] - M) * invL;
    }
}

// ---------------- small split-K SGEMM: C_part[ks] = A(64xK) * W(1024xK)^T ---
template<int K, int NSK>
__device__ __forceinline__ void gemm_body(const float* __restrict__ A,
                                          const float* __restrict__ W,
                                          float* __restrict__ Cp)
{
    __shared__ float As[32][68];   // [k][b], padded
    __shared__ float Ws[32][68];   // [k][j], padded
    const int jb = blockIdx.x * 64;
    const int kbase0 = blockIdx.y * (K / NSK);
    const int t = threadIdx.x;
    const int tx = t & 15, ty = t >> 4;
    float c[4][4];
#pragma unroll
    for (int i = 0; i < 4; i++)
#pragma unroll
        for (int j = 0; j < 4; j++) c[i][j] = 0.f;

#pragma unroll 1
    for (int kb = 0; kb < K / NSK; kb += 32) {
        const int kbase = kbase0 + kb;
#pragma unroll
        for (int i = 0; i < 8; i++) {
            int g = t + i * 256;
            As[g & 31][g >> 5] = A[(g >> 5) * K + kbase + (g & 31)];
        }
#pragma unroll
        for (int i = 0; i < 8; i++) {
            int g = t + i * 256;
            Ws[g & 31][g >> 5] = W[(jb + (g >> 5)) * K + kbase + (g & 31)];
        }
        __syncthreads();
#pragma unroll
        for (int kk = 0; kk < 32; kk++) {
            float4 av = *(const float4*)&As[kk][ty * 4];
            float4 wv = *(const float4*)&Ws[kk][tx * 4];
            c[0][0] += av.x * wv.x; c[0][1] += av.x * wv.y; c[0][2] += av.x * wv.z; c[0][3] += av.x * wv.w;
            c[1][0] += av.y * wv.x; c[1][1] += av.y * wv.y; c[1][2] += av.y * wv.z; c[1][3] += av.y * wv.w;
            c[2][0] += av.z * wv.x; c[2][1] += av.z * wv.y; c[2][2] += av.z * wv.z; c[2][3] += av.z * wv.w;
            c[3][0] += av.w * wv.x; c[3][1] += av.w * wv.y; c[3][2] += av.w * wv.z; c[3][3] += av.w * wv.w;
        }
        __syncthreads();
    }
#pragma unroll
    for (int mi = 0; mi < 4; mi++) {
        float4 v = make_float4(c[mi][0], c[mi][1], c[mi][2], c[mi][3]);
        *(float4*)(Cp + ((long)blockIdx.y * B + ty * 4 + mi) * H + jb + tx * 4) = v;
    }
}

__global__ __launch_bounds__(256) void k_fc1(const float* __restrict__ W)
{
    gemm_body<2 * H, NSK1>(g_xin, W, g_part1);
}

__global__ __launch_bounds__(256) void k_fc2(const float* __restrict__ W)
{
    gemm_body<H, NSK2>(g_t, W, g_part2);
}

// ---------------- reduce fc1 partials + bias (256 CTAs, coalesced) ---------
__global__ __launch_bounds__(256) void k_red1(const float* __restrict__ fc1_b)
{
    const int b = blockIdx.y;
    const int j = blockIdx.x * 256 + threadIdx.x;   // blockIdx.x in 0..3
    float y = fc1_b[j];
#pragma unroll
    for (int s2 = 0; s2 < NSK1; s2++)
        y += g_part1[((long)s2 * B + b) * H + j];
    g_y[b * H + j] = y;
}

// ---------------- batch-norm (training stats, biased var) + tanh -----------
__global__ __launch_bounds__(256) void k_bn(const float* __restrict__ gamma,
                                            const float* __restrict__ beta)
{
    const int t  = threadIdx.x;
    const int jj = t >> 6;            // 0..3
    const int b  = t & 63;
    const int j  = blockIdx.x * 4 + jj;
    float y  = g_y[b * H + j];
    float s1 = y, s2 = y * y;
#pragma unroll
    for (int off = 16; off >= 1; off >>= 1) {
        s1 += __shfl_xor_sync(0xffffffffu, s1, off);
        s2 += __shfl_xor_sync(0xffffffffu, s2, off);
    }
    __shared__ float sm1[8], sm2[8];
    const int warp = t >> 5;
    if ((t & 31) == 0) { sm1[warp] = s1; sm2[warp] = s2; }
    __syncthreads();
    float S1 = sm1[jj * 2] + sm1[jj * 2 + 1];
    float S2 = sm2[jj * 2] + sm2[jj * 2 + 1];
    float mean = S1 * (1.f / 64.f);
    float var  = S2 * (1.f / 64.f) - mean * mean;
    float rstd = rsqrtf(var + 1e-5f);
    g_t[b * H + j] = tanhf((y - mean) * rstd * gamma[j] + beta[j]);
}

// ---------------- reduce fc2 partials + bias -> x output (256 CTAs) --------
__global__ __launch_bounds__(256) void k_out(const float* __restrict__ fc2_b,
                                             float* __restrict__ x)
{
    const int b = blockIdx.y;
    const int j = blockIdx.x * 256 + threadIdx.x;
    float v = fc2_b[j];
#pragma unroll
    for (int s2 = 0; s2 < NSK2; s2++)
        v += g_part2[((long)s2 * B + b) * H + j];
    x[b * H + j] = v;
}

// ---------------------------------------------------------------------------
extern "C" void kernel_launch(void* const* d_in, const int* in_sizes, int n_in,
                              void* d_out, int out_size)
{
    (void)in_sizes; (void)n_in; (void)out_size;
    const float* ctx   = (const float*)d_in[0];
    const float* key   = (const float*)d_in[1];
    const float* mask  = (const float*)d_in[2];
    const float* fc1_w = (const float*)d_in[3];
    const float* fc1_b = (const float*)d_in[4];
    const float* gamma = (const float*)d_in[5];
    const float* beta  = (const float*)d_in[6];
    const float* fc2_w = (const float*)d_in[7];
    const float* fc2_b = (const float*)d_in[8];

    float* out    = (float*)d_out;
    float* x_out  = out;            // (B, H)
    float* at_out = out + B * H;    // (B, S)

    k_attn  <<<dim3(NSPLIT, B), 256>>>(ctx, key, mask, at_out);
    k_finish<<<B, 256>>>(key, at_out);
    k_fc1   <<<dim3(H / 64, NSK1), 256>>>(fc1_w);
    k_red1  <<<dim3(4, B), 256>>>(fc1_b);
    k_bn    <<<H / 4, 256>>>(gamma, beta);
    k_fc2   <<<dim3(H / 64, NSK2), 256>>>(fc2_w);
    k_out   <<<dim3(4, B), 256>>>(fc2_b, x_out);
}